// round 5
// baseline (speedup 1.0000x reference)
#include <cuda_runtime.h>
#include <cuda_bf16.h>
#include <math.h>

// Problem constants
#define BGRAPH 128
#define NNODE  512
#define NN     (BGRAPH*NNODE)      // 65536
#define DFEAT  128
#define EDGES  524288
#define KEEP1  410
#define KEEP2  328
#define BUCKET_CAP 32

// ---------------- scratch (device globals; no runtime allocation) ----------------
__device__ float g_h  [NN*DFEAT];   // conv1 output (then gated in place)
__device__ float g_h2 [NN*DFEAT];   // conv2 output
__device__ int   g_deg[NN];
__device__ int   g_bucket[NN*BUCKET_CAP];
__device__ int   g_ovf_cnt;
__device__ int   g_ovf_d[EDGES];
__device__ int   g_ovf_s[EDGES];
__device__ unsigned char g_m1[NN];
__device__ float g_x1[BGRAPH*256];
__device__ float g_x2[BGRAPH*256];

// ---------------- packed fp32x2 helpers (Blackwell) ----------------
__device__ __forceinline__ unsigned long long pk2(float x) {
    unsigned long long d;
    asm("mov.b64 %0, {%1, %1};" : "=l"(d) : "f"(x));
    return d;
}
__device__ __forceinline__ unsigned long long pack2(float lo, float hi) {
    unsigned long long d;
    asm("mov.b64 %0, {%1, %2};" : "=l"(d) : "f"(lo), "f"(hi));
    return d;
}
__device__ __forceinline__ unsigned long long ffma2(unsigned long long a,
                                                    unsigned long long b,
                                                    unsigned long long c) {
    unsigned long long d;
    asm("fma.rn.f32x2 %0, %1, %2, %3;" : "=l"(d) : "l"(a), "l"(b), "l"(c));
    return d;
}
__device__ __forceinline__ void unpk2(unsigned long long v, float& lo, float& hi) {
    asm("mov.b64 {%0, %1}, %2;" : "=f"(lo), "=f"(hi) : "l"(v));
}

// ---------------- bucketed edge build (replaces hist+scan+scatter CSR) ----------------
__global__ void zero_kernel() {
    int i = blockIdx.x * blockDim.x + threadIdx.x;
    if (i < NN) g_deg[i] = 0;
    if (i == 0) g_ovf_cnt = 0;
}

__global__ void bucket_scatter_kernel(const int* __restrict__ src,
                                      const int* __restrict__ dst) {
    int i = blockIdx.x * blockDim.x + threadIdx.x;
    if (i < EDGES) {
        int d = dst[i];
        int s = src[i];
        int pos = atomicAdd(&g_deg[d], 1);
        if (pos < BUCKET_CAP) {
            g_bucket[d * BUCKET_CAP + pos] = s;
        } else {
            int o = atomicAdd(&g_ovf_cnt, 1);
            g_ovf_d[o] = d;
            g_ovf_s[o] = s;
        }
    }
}

// ---------------- warp gather of one node's neighbor sum (float4 per lane) ----------
__device__ __forceinline__ float4 gather_node(const float4* __restrict__ f4,
                                              int node, int lane) {
    int nv = __ldg(&g_deg[node]);
    int m = min(nv, BUCKET_CAP);
    int idx = 0;
    if (lane < m) idx = __ldg(&g_bucket[node * BUCKET_CAP + lane]);
    float4 a = make_float4(0.f, 0.f, 0.f, 0.f);
    int e = 0;
    for (; e + 4 <= m; e += 4) {
        int i0 = __shfl_sync(0xffffffffu, idx, e);
        int i1 = __shfl_sync(0xffffffffu, idx, e + 1);
        int i2 = __shfl_sync(0xffffffffu, idx, e + 2);
        int i3 = __shfl_sync(0xffffffffu, idx, e + 3);
        float4 v0 = __ldg(f4 + (size_t)i0 * 32 + lane);
        float4 v1 = __ldg(f4 + (size_t)i1 * 32 + lane);
        float4 v2 = __ldg(f4 + (size_t)i2 * 32 + lane);
        float4 v3 = __ldg(f4 + (size_t)i3 * 32 + lane);
        a.x += (v0.x + v1.x) + (v2.x + v3.x);
        a.y += (v0.y + v1.y) + (v2.y + v3.y);
        a.z += (v0.z + v1.z) + (v2.z + v3.z);
        a.w += (v0.w + v1.w) + (v2.w + v3.w);
    }
    for (; e < m; ++e) {
        int i0 = __shfl_sync(0xffffffffu, idx, e);
        float4 v0 = __ldg(f4 + (size_t)i0 * 32 + lane);
        a.x += v0.x; a.y += v0.y; a.z += v0.z; a.w += v0.w;
    }
    if (nv > BUCKET_CAP) {   // correctness fallback; ~never taken
        int oc = g_ovf_cnt;
        for (int t = 0; t < oc; ++t) {
            if (g_ovf_d[t] == node) {
                float4 v0 = __ldg(f4 + (size_t)g_ovf_s[t] * 32 + lane);
                a.x += v0.x; a.y += v0.y; a.z += v0.z; a.w += v0.w;
            }
        }
    }
    return a;
}

// ---------------- fused gather + conv GEMM: out = relu(A1@Wr + agg@Wn + b) --------
// Tile 128x128, K=256. Gather phase builds agg in smem pre-packed as f32x2
// row-pairs (aggP[k][pair]), so both halves of the mainloop use LDS.64 A reads.
// Double-buffered As/Ws staging: one barrier per chunk.
#define AGGP_PITCH 65                  // u64 pitch (pad to dodge bank conflicts on STS)
#define AGGP_U64   (128*AGGP_PITCH)    // 8320 u64 = 16640 floats
#define SMEM_FLOATS (AGGP_U64*2 + 2*1024 + 2*1024)
#define SMEM_BYTES  (SMEM_FLOATS*4)    // 82944 bytes

template<int LAYER>
__global__ void __launch_bounds__(256, 2)
conv_fused_kernel(const float* __restrict__ A1in,
                  const float* __restrict__ Wr,
                  const float* __restrict__ Wn,
                  const float* __restrict__ bias) {
    extern __shared__ float smemf[];
    unsigned long long* aggP = (unsigned long long*)smemf;
    float* AsBuf = smemf + AGGP_U64 * 2;      // 2 x [8][128]
    float* WsBuf = AsBuf + 2 * 1024;          // 2 x [8][128]

    const float* A1 = (LAYER == 1) ? A1in : g_h;   // gather source == conv input
    float* Out = (LAYER == 1) ? g_h : g_h2;

    int tid = threadIdx.x;
    int lane = tid & 31;
    int w = tid >> 5;          // 8 warps
    int cx = lane;             // output cols cx + 32*j
    int ry = w;                // output rows ry*16 .. ry*16+15
    int row0 = blockIdx.x * 128;
    int lrow = tid >> 1;       // A loader row
    int lk4 = (tid & 1) * 4;   // A loader k sub-offset

    const float4* f4 = (const float4*)A1;

    // ---- gather phase: warp w builds row pairs pr = w*8 .. w*8+7 ----
    for (int pr = w * 8; pr < w * 8 + 8; ++pr) {
        float4 aE = gather_node(f4, row0 + 2 * pr, lane);
        float4 aO = gather_node(f4, row0 + 2 * pr + 1, lane);
        int k = 4 * lane;
        aggP[(k + 0) * AGGP_PITCH + pr] = pack2(aE.x, aO.x);
        aggP[(k + 1) * AGGP_PITCH + pr] = pack2(aE.y, aO.y);
        aggP[(k + 2) * AGGP_PITCH + pr] = pack2(aE.z, aO.z);
        aggP[(k + 3) * AGGP_PITCH + pr] = pack2(aE.w, aO.w);
    }

    // ---- preload chunk 0 (A1, Wr) into buffer 0 ----
    {
        float4 av = *(const float4*)&A1[(size_t)(row0 + lrow) * 128 + lk4];
        float4 wv = *(const float4*)&Wr[(size_t)ry * 128 + cx * 4];
        AsBuf[(lk4 + 0) * 128 + lrow] = av.x;
        AsBuf[(lk4 + 1) * 128 + lrow] = av.y;
        AsBuf[(lk4 + 2) * 128 + lrow] = av.z;
        AsBuf[(lk4 + 3) * 128 + lrow] = av.w;
        *(float4*)&WsBuf[ry * 128 + cx * 4] = wv;
    }
    __syncthreads();

    unsigned long long acc[8][4];
#pragma unroll
    for (int r = 0; r < 8; ++r)
#pragma unroll
        for (int j = 0; j < 4; ++j) acc[r][j] = 0ull;

#pragma unroll 1
    for (int chunk = 0; chunk < 32; ++chunk) {
        int cur = chunk & 1;
        // prefetch next chunk into registers
        float4 nav, nwv;
        bool hasNext = (chunk + 1) < 32;
        bool nextA = (chunk + 1) < 16;
        if (hasNext) {
            int nc = chunk + 1;
            const float* W = (nc < 16) ? Wr : Wn;
            int k0n = (nc & 15) * 8;
            nwv = *(const float4*)&W[(size_t)(k0n + ry) * 128 + cx * 4];
            if (nextA)
                nav = *(const float4*)&A1[(size_t)(row0 + lrow) * 128 + k0n + lk4];
        }

        // compute on current buffer
        const float* Ws = WsBuf + cur * 1024;
        if (chunk < 16) {
            const float* As = AsBuf + cur * 1024;
#pragma unroll
            for (int k = 0; k < 8; ++k) {
                unsigned long long ap[8];
#pragma unroll
                for (int r = 0; r < 8; ++r)
                    ap[r] = *(const unsigned long long*)&As[k * 128 + ry * 16 + 2 * r];
#pragma unroll
                for (int j = 0; j < 4; ++j) {
                    unsigned long long wp = pk2(Ws[k * 128 + cx + 32 * j]);
#pragma unroll
                    for (int r = 0; r < 8; ++r)
                        acc[r][j] = ffma2(ap[r], wp, acc[r][j]);
                }
            }
        } else {
            int k0 = (chunk & 15) * 8;
#pragma unroll
            for (int k = 0; k < 8; ++k) {
                unsigned long long ap[8];
#pragma unroll
                for (int r = 0; r < 8; ++r)
                    ap[r] = aggP[(k0 + k) * AGGP_PITCH + ry * 8 + r];
#pragma unroll
                for (int j = 0; j < 4; ++j) {
                    unsigned long long wp = pk2(Ws[k * 128 + cx + 32 * j]);
#pragma unroll
                    for (int r = 0; r < 8; ++r)
                        acc[r][j] = ffma2(ap[r], wp, acc[r][j]);
                }
            }
        }

        // store prefetched data into the other buffer
        if (hasNext) {
            int nxt = cur ^ 1;
            float* Wd = WsBuf + nxt * 1024;
            *(float4*)&Wd[ry * 128 + cx * 4] = nwv;
            if (nextA) {
                float* Ad = AsBuf + nxt * 1024;
                Ad[(lk4 + 0) * 128 + lrow] = nav.x;
                Ad[(lk4 + 1) * 128 + lrow] = nav.y;
                Ad[(lk4 + 2) * 128 + lrow] = nav.z;
                Ad[(lk4 + 3) * 128 + lrow] = nav.w;
            }
            __syncthreads();
        }
    }

    // ---- epilogue: bias + relu ----
#pragma unroll
    for (int j = 0; j < 4; ++j) {
        int col = cx + 32 * j;
        float bb = __ldg(&bias[col]);
#pragma unroll
        for (int r = 0; r < 8; ++r) {
            float lo, hi;
            unpk2(acc[r][j], lo, hi);
            int row = row0 + ry * 16 + 2 * r;
            Out[(size_t)row * 128 + col]       = fmaxf(lo + bb, 0.f);
            Out[(size_t)(row + 1) * 128 + col] = fmaxf(hi + bb, 0.f);
        }
    }
}

// ---------------- pool: score + topk + gate + readout (one block per graph) ----------------
template<int LAYER>
__global__ void __launch_bounds__(512)
pool_kernel(const float* __restrict__ p) {
    constexpr int KK = (LAYER == 1) ? KEEP1 : KEEP2;
    float* h = (LAYER == 1) ? g_h : g_h2;
    float* xout = (LAYER == 1) ? g_x1 : g_x2;

    int b = blockIdx.x;
    int tid = threadIdx.x;
    int lane = tid & 31, w = tid >> 5;   // 16 warps

    __shared__ float sval[512];
    __shared__ float ssort[512];
    __shared__ float sgate[512];
    __shared__ int   ssel[512];
    __shared__ int   sscan[512];
    __shared__ float rmax[16 * 128];
    __shared__ float rsum[16 * 128];

    float p0 = p[lane], p1v = p[lane + 32], p2v = p[lane + 64], p3v = p[lane + 96];
    float n2 = p0 * p0 + p1v * p1v + p2v * p2v + p3v * p3v;
#pragma unroll
    for (int o = 16; o; o >>= 1) n2 += __shfl_xor_sync(0xffffffffu, n2, o);
    float inv = rsqrtf(n2);

    float* hb = h + (size_t)b * NNODE * 128;

    // scores: warp per node
    for (int n = w; n < NNODE; n += 16) {
        const float* r = hb + n * 128;
        float acc = r[lane] * p0 + r[lane + 32] * p1v + r[lane + 64] * p2v + r[lane + 96] * p3v;
#pragma unroll
        for (int o = 16; o; o >>= 1) acc += __shfl_xor_sync(0xffffffffu, acc, o);
        if (lane == 0) {
            float s = acc * inv;
            if (LAYER == 2 && !g_m1[b * NNODE + n]) s = -INFINITY;
            sval[n] = s;
        }
    }
    __syncthreads();

    // bitonic sort (descending) to find threshold = K-th largest
    ssort[tid] = sval[tid];
    __syncthreads();
    for (int k2 = 2; k2 <= 512; k2 <<= 1) {
        for (int j = k2 >> 1; j > 0; j >>= 1) {
            int ixj = tid ^ j;
            float a = ssort[tid];
            float bv = ssort[ixj];
            bool desc = ((tid & k2) == 0);
            bool isLower = (tid < ixj);
            float res = (desc == isLower) ? fmaxf(a, bv) : fminf(a, bv);
            __syncthreads();
            ssort[tid] = res;
            __syncthreads();
        }
    }
    float t = ssort[KK - 1];

    // exact selection with lowest-index tie-break (matches lax.top_k)
    float s = sval[tid];
    int fgt = (s > t) ? 1 : 0;
    int feq = (s == t) ? 1 : 0;
    sscan[tid] = (fgt << 16) | feq;
    __syncthreads();
    for (int off = 1; off < 512; off <<= 1) {
        int v = (tid >= off) ? sscan[tid - off] : 0;
        __syncthreads();
        sscan[tid] += v;
        __syncthreads();
    }
    int totgt = sscan[511] >> 16;
    int preeq = (sscan[tid] & 0xffff) - feq;
    int sel = fgt | (feq && (preeq < KK - totgt));
    ssel[tid] = sel;
    sgate[tid] = sel ? tanhf(s) : 0.f;
    if (LAYER == 1) g_m1[b * NNODE + tid] = (unsigned char)sel;
    __syncthreads();

    // gate (+writeback for layer1) + readout (max & mean over kept nodes)
    float mx0 = -INFINITY, mx1 = -INFINITY, mx2 = -INFINITY, mx3 = -INFINITY;
    float sm0 = 0.f, sm1 = 0.f, sm2 = 0.f, sm3 = 0.f;
    for (int n = w; n < NNODE; n += 16) {
        float g = sgate[n];
        int se = ssel[n];
        float* r = hb + n * 128;
        float v0 = r[lane] * g;
        float v1 = r[lane + 32] * g;
        float v2 = r[lane + 64] * g;
        float v3 = r[lane + 96] * g;
        if (LAYER == 1) {
            r[lane] = v0; r[lane + 32] = v1; r[lane + 64] = v2; r[lane + 96] = v3;
        }
        if (se) {
            mx0 = fmaxf(mx0, v0); mx1 = fmaxf(mx1, v1);
            mx2 = fmaxf(mx2, v2); mx3 = fmaxf(mx3, v3);
        }
        sm0 += v0; sm1 += v1; sm2 += v2; sm3 += v3;
    }
    rmax[w * 128 + lane]      = mx0;
    rmax[w * 128 + lane + 32] = mx1;
    rmax[w * 128 + lane + 64] = mx2;
    rmax[w * 128 + lane + 96] = mx3;
    rsum[w * 128 + lane]      = sm0;
    rsum[w * 128 + lane + 32] = sm1;
    rsum[w * 128 + lane + 64] = sm2;
    rsum[w * 128 + lane + 96] = sm3;
    __syncthreads();
    if (tid < 128) {
        float M = -INFINITY, S = 0.f;
#pragma unroll
        for (int i = 0; i < 16; ++i) {
            M = fmaxf(M, rmax[i * 128 + tid]);
            S += rsum[i * 128 + tid];
        }
        xout[b * 256 + tid] = M;
        xout[b * 256 + 128 + tid] = S / (float)KK;
    }
}

// ---------------- MLP head ----------------
__global__ void __launch_bounds__(128)
head_kernel(const float* __restrict__ lw1, const float* __restrict__ lb1,
            const float* __restrict__ lw2, const float* __restrict__ lb2,
            const float* __restrict__ lw3, const float* __restrict__ lb3,
            float* __restrict__ out) {
    int b = blockIdx.x;
    int tid = threadIdx.x;   // 128
    __shared__ float z[256], z1[128], z2[64];
    z[tid]       = g_x1[b * 256 + tid]       + g_x2[b * 256 + tid];
    z[tid + 128] = g_x1[b * 256 + 128 + tid] + g_x2[b * 256 + 128 + tid];
    __syncthreads();
    float a = lb1[tid];
#pragma unroll 8
    for (int i = 0; i < 256; ++i) a += z[i] * lw1[i * 128 + tid];
    z1[tid] = fmaxf(a, 0.f);
    __syncthreads();
    if (tid < 64) {
        float a2 = lb2[tid];
#pragma unroll 8
        for (int i = 0; i < 128; ++i) a2 += z1[i] * lw2[i * 64 + tid];
        z2[tid] = fmaxf(a2, 0.f);
    }
    __syncthreads();
    if (tid == 0) {
        float a3 = lb3[0];
#pragma unroll 8
        for (int i = 0; i < 64; ++i) a3 += z2[i] * lw3[i];
        out[b] = 1.f / (1.f + expf(-a3));
    }
}

// ---------------- launch ----------------
extern "C" void kernel_launch(void* const* d_in, const int* in_sizes, int n_in,
                              void* d_out, int out_size) {
    const float* x   = (const float*)d_in[0];
    const int*   ei  = (const int*)d_in[1];
    const float* W1r = (const float*)d_in[2];
    const float* W1n = (const float*)d_in[3];
    const float* b1  = (const float*)d_in[4];
    const float* p1  = (const float*)d_in[5];
    const float* W2r = (const float*)d_in[6];
    const float* W2n = (const float*)d_in[7];
    const float* b2  = (const float*)d_in[8];
    const float* p2  = (const float*)d_in[9];
    const float* lw1 = (const float*)d_in[10];
    const float* lb1 = (const float*)d_in[11];
    const float* lw2 = (const float*)d_in[12];
    const float* lb2 = (const float*)d_in[13];
    const float* lw3 = (const float*)d_in[14];
    const float* lb3 = (const float*)d_in[15];
    float* out = (float*)d_out;

    const int* src = ei;
    const int* dst = ei + EDGES;

    // opt-in to >48KB dynamic smem (idempotent; host-side, not captured)
    cudaFuncSetAttribute(conv_fused_kernel<1>,
                         cudaFuncAttributeMaxDynamicSharedMemorySize, SMEM_BYTES);
    cudaFuncSetAttribute(conv_fused_kernel<2>,
                         cudaFuncAttributeMaxDynamicSharedMemorySize, SMEM_BYTES);

    // edge buckets (edges are an input, rebuilt every call — stateless)
    zero_kernel<<<NN / 256, 256>>>();
    bucket_scatter_kernel<<<EDGES / 256, 256>>>(src, dst);

    // conv1 (fused gather+GEMM) + pool1
    conv_fused_kernel<1><<<NN / 128, 256, SMEM_BYTES>>>(x, W1r, W1n, b1);
    pool_kernel<1><<<BGRAPH, 512>>>(p1);

    // conv2 (fused gather+GEMM on gated h) + pool2
    conv_fused_kernel<2><<<NN / 128, 256, SMEM_BYTES>>>(nullptr, W2r, W2n, b2);
    pool_kernel<2><<<BGRAPH, 512>>>(p2);

    // head
    head_kernel<<<BGRAPH, 128>>>(lw1, lb1, lw2, lb2, lw3, lb3, out);
}

// round 6
// speedup vs baseline: 1.1520x; 1.1520x over previous
#include <cuda_runtime.h>
#include <cuda_bf16.h>
#include <math.h>

// Problem constants
#define BGRAPH 128
#define NNODE  512
#define NN     (BGRAPH*NNODE)      // 65536
#define DFEAT  128
#define EDGES  524288
#define KEEP1  410
#define KEEP2  328
#define BUCKET_CAP 32

// ---------------- scratch (device globals; no runtime allocation) ----------------
__device__ float g_agg[NN*DFEAT];   // aggregated neighbor features
__device__ float g_h  [NN*DFEAT];   // conv1 output (gated in place by pool1)
__device__ float g_h2 [NN*DFEAT];   // conv2 output
__device__ float g_score[NN];       // node scores (written by GEMM epilogue)
__device__ int   g_deg[NN];
__device__ int   g_bucket[NN*BUCKET_CAP];
__device__ int   g_ovf_cnt;
__device__ int   g_ovf_d[EDGES];
__device__ int   g_ovf_s[EDGES];
__device__ unsigned char g_m1[NN];
__device__ float g_x1[BGRAPH*256];
__device__ float g_x2[BGRAPH*256];

// ---------------- packed fp32x2 helpers (Blackwell) ----------------
__device__ __forceinline__ unsigned long long pk2(float x) {
    unsigned long long d;
    asm("mov.b64 %0, {%1, %1};" : "=l"(d) : "f"(x));
    return d;
}
__device__ __forceinline__ unsigned long long ffma2(unsigned long long a,
                                                    unsigned long long b,
                                                    unsigned long long c) {
    unsigned long long d;
    asm("fma.rn.f32x2 %0, %1, %2, %3;" : "=l"(d) : "l"(a), "l"(b), "l"(c));
    return d;
}
__device__ __forceinline__ void unpk2(unsigned long long v, float& lo, float& hi) {
    asm("mov.b64 {%0, %1}, %2;" : "=f"(lo), "=f"(hi) : "l"(v));
}

// ---------------- bucketed edge build ----------------
__global__ void zero_kernel() {
    int i = blockIdx.x * blockDim.x + threadIdx.x;
    if (i < NN) g_deg[i] = 0;
    if (i == 0) g_ovf_cnt = 0;
}

__global__ void bucket_scatter_kernel(const int* __restrict__ src,
                                      const int* __restrict__ dst) {
    int i = blockIdx.x * blockDim.x + threadIdx.x;
    if (i < EDGES) {
        int d = dst[i];
        int s = src[i];
        int pos = atomicAdd(&g_deg[d], 1);
        if (pos < BUCKET_CAP) {
            g_bucket[d * BUCKET_CAP + pos] = s;
        } else {
            int o = atomicAdd(&g_ovf_cnt, 1);
            g_ovf_d[o] = d;
            g_ovf_s[o] = s;
        }
    }
}

// ---------------- aggregation with graph-local smem staging ----------------
// Block = (feature chunk cx32, graph b). Stage the graph's 512x32 feature slab
// in smem (64KB, pitch 32 -> conflict-free), then every neighbor read is smem.
#define AGG_SMEM_BYTES (NNODE*32*4)   // 65536

template<int LAYER>
__global__ void __launch_bounds__(256)
agg_stage_kernel(const float* __restrict__ xin) {
    extern __shared__ float sf[];     // [512][32]
    const float* feat = (LAYER == 1) ? xin : g_h;
    int b = blockIdx.y;
    int c = blockIdx.x;               // feature chunk, 0..3
    int tid = threadIdx.x;
    int lane = tid & 31, w = tid >> 5;    // 8 warps
    int base = b * NNODE;

    // stage: 8 threads per node, float4 each
    {
        int nsub = tid >> 3;          // 0..31
        int f4o = (tid & 7);          // 0..7 -> floats f4o*4..+3
        for (int n = nsub; n < NNODE; n += 32) {
            float4 v = __ldg((const float4*)&feat[(size_t)(base + n) * 128 + c * 32 + f4o * 4]);
            *(float4*)&sf[n * 32 + f4o * 4] = v;
        }
    }
    __syncthreads();

    // gather: warp per node, lane = feature
    for (int n = w; n < NNODE; n += 8) {
        int node = base + n;
        int nv = __ldg(&g_deg[node]);
        int m = min(nv, BUCKET_CAP);
        int idx = 0;
        if (lane < m) idx = __ldg(&g_bucket[node * BUCKET_CAP + lane]) - base;
        float a = 0.f;
        int e = 0;
        for (; e + 4 <= m; e += 4) {
            int i0 = __shfl_sync(0xffffffffu, idx, e);
            int i1 = __shfl_sync(0xffffffffu, idx, e + 1);
            int i2 = __shfl_sync(0xffffffffu, idx, e + 2);
            int i3 = __shfl_sync(0xffffffffu, idx, e + 3);
            a += (sf[i0 * 32 + lane] + sf[i1 * 32 + lane])
               + (sf[i2 * 32 + lane] + sf[i3 * 32 + lane]);
        }
        for (; e < m; ++e) {
            int i0 = __shfl_sync(0xffffffffu, idx, e);
            a += sf[i0 * 32 + lane];
        }
        if (nv > BUCKET_CAP) {   // correctness fallback; ~never taken
            int oc = g_ovf_cnt;
            for (int t = 0; t < oc; ++t) {
                if (g_ovf_d[t] == node)
                    a += __ldg(&feat[(size_t)g_ovf_s[t] * 128 + c * 32 + lane]);
            }
        }
        g_agg[(size_t)node * 128 + c * 32 + lane] = a;
    }
}

// ---------------- conv GEMM: out = relu(A1@Wr + A2@Wn + b); score epilogue ----
// Tile 128x128, K=256 (two 128 sources), 256 threads, f32x2 packed FMA.
// (Mainloop identical to the proven round-3 kernel.)
template<int LAYER>
__global__ void __launch_bounds__(256, 2)
conv_gemm_kernel(const float* __restrict__ A1in,
                 const float* __restrict__ Wr,
                 const float* __restrict__ Wn,
                 const float* __restrict__ bias,
                 const float* __restrict__ p) {
    const float* A1 = (LAYER == 1) ? A1in : g_h;
    const float* A2 = g_agg;
    float* Out = (LAYER == 1) ? g_h : g_h2;

    __shared__ float As[8][128];
    __shared__ float Ws[8][128];

    int tid = threadIdx.x;
    int cx = tid & 31;        // column group: cols cx + 32*j
    int ry = tid >> 5;        // row group: rows ry*16 .. ry*16+15 (8 pairs)
    int row0 = blockIdx.x * 128;
    int lrow = tid >> 1;              // A loader row 0..127
    int lk4 = (tid & 1) * 4;          // A loader k sub-offset

    unsigned long long acc[8][4];
#pragma unroll
    for (int r = 0; r < 8; ++r)
#pragma unroll
        for (int j = 0; j < 4; ++j) acc[r][j] = 0ull;

#pragma unroll 1
    for (int chunk = 0; chunk < 32; ++chunk) {
        const float* A = (chunk < 16) ? A1 : A2;
        const float* W = (chunk < 16) ? Wr : Wn;
        int k0 = (chunk & 15) * 8;

        float4 av = *(const float4*)&A[(size_t)(row0 + lrow) * 128 + k0 + lk4];
        float4 wv = *(const float4*)&W[(size_t)(k0 + ry) * 128 + cx * 4];

        __syncthreads();   // previous iteration's reads done
        As[lk4 + 0][lrow] = av.x;
        As[lk4 + 1][lrow] = av.y;
        As[lk4 + 2][lrow] = av.z;
        As[lk4 + 3][lrow] = av.w;
        *(float4*)&Ws[ry][cx * 4] = wv;
        __syncthreads();

#pragma unroll
        for (int k = 0; k < 8; ++k) {
            unsigned long long ap[8];
#pragma unroll
            for (int r = 0; r < 8; ++r)
                ap[r] = *(const unsigned long long*)&As[k][ry * 16 + 2 * r];
#pragma unroll
            for (int j = 0; j < 4; ++j) {
                unsigned long long wp = pk2(Ws[k][cx + 32 * j]);
#pragma unroll
                for (int r = 0; r < 8; ++r)
                    acc[r][j] = ffma2(ap[r], wp, acc[r][j]);
            }
        }
    }

    // ---- epilogue: bias + relu + per-row score (h . p / ||p||) ----
    float pv[4];
    float pn = 0.f;
#pragma unroll
    for (int j = 0; j < 4; ++j) {
        pv[j] = __ldg(&p[cx + 32 * j]);
        pn += pv[j] * pv[j];
    }
#pragma unroll
    for (int o = 16; o; o >>= 1) pn += __shfl_xor_sync(0xffffffffu, pn, o);
    float pinv = rsqrtf(pn);

#pragma unroll
    for (int r = 0; r < 8; ++r) {
        float slo = 0.f, shi = 0.f;
        int row = row0 + ry * 16 + 2 * r;
#pragma unroll
        for (int j = 0; j < 4; ++j) {
            int col = cx + 32 * j;
            float bb = __ldg(&bias[col]);
            float lo, hi;
            unpk2(acc[r][j], lo, hi);
            lo = fmaxf(lo + bb, 0.f);
            hi = fmaxf(hi + bb, 0.f);
            Out[(size_t)row * 128 + col]       = lo;
            Out[(size_t)(row + 1) * 128 + col] = hi;
            slo += lo * pv[j];
            shi += hi * pv[j];
        }
#pragma unroll
        for (int o = 16; o; o >>= 1) {
            slo += __shfl_xor_sync(0xffffffffu, slo, o);
            shi += __shfl_xor_sync(0xffffffffu, shi, o);
        }
        if (cx == 0) {
            g_score[row]     = slo * pinv;
            g_score[row + 1] = shi * pinv;
        }
    }
}

// ---------------- pool: topk + gate + readout (one block per graph) ----------------
template<int LAYER>
__global__ void __launch_bounds__(512)
pool_kernel() {
    constexpr int KK = (LAYER == 1) ? KEEP1 : KEEP2;
    float* h = (LAYER == 1) ? g_h : g_h2;
    float* xout = (LAYER == 1) ? g_x1 : g_x2;

    int b = blockIdx.x;
    int tid = threadIdx.x;
    int lane = tid & 31, w = tid >> 5;   // 16 warps

    __shared__ float sval[512];
    __shared__ float ssort[512];
    __shared__ float sgate[512];
    __shared__ int   ssel[512];
    __shared__ int   sscan[512];
    __shared__ float rmax[16 * 128];
    __shared__ float rsum[16 * 128];

    float* hb = h + (size_t)b * NNODE * 128;

    // scores: precomputed by GEMM epilogue
    {
        float s = g_score[b * NNODE + tid];
        if (LAYER == 2 && !g_m1[b * NNODE + tid]) s = -INFINITY;
        sval[tid] = s;
        ssort[tid] = s;
    }
    __syncthreads();

    // bitonic sort (descending) to find threshold = K-th largest
    for (int k2 = 2; k2 <= 512; k2 <<= 1) {
        for (int j = k2 >> 1; j > 0; j >>= 1) {
            int ixj = tid ^ j;
            float a = ssort[tid];
            float bv = ssort[ixj];
            bool desc = ((tid & k2) == 0);
            bool isLower = (tid < ixj);
            float res = (desc == isLower) ? fmaxf(a, bv) : fminf(a, bv);
            __syncthreads();
            ssort[tid] = res;
            __syncthreads();
        }
    }
    float t = ssort[KK - 1];

    // exact selection with lowest-index tie-break (matches lax.top_k)
    float s = sval[tid];
    int fgt = (s > t) ? 1 : 0;
    int feq = (s == t) ? 1 : 0;
    sscan[tid] = (fgt << 16) | feq;
    __syncthreads();
    for (int off = 1; off < 512; off <<= 1) {
        int v = (tid >= off) ? sscan[tid - off] : 0;
        __syncthreads();
        sscan[tid] += v;
        __syncthreads();
    }
    int totgt = sscan[511] >> 16;
    int preeq = (sscan[tid] & 0xffff) - feq;
    int sel = fgt | (feq && (preeq < KK - totgt));
    ssel[tid] = sel;
    sgate[tid] = sel ? tanhf(s) : 0.f;
    if (LAYER == 1) g_m1[b * NNODE + tid] = (unsigned char)sel;
    __syncthreads();

    // gate (+writeback for layer1) + readout (max & mean over kept nodes)
    float mx0 = -INFINITY, mx1 = -INFINITY, mx2 = -INFINITY, mx3 = -INFINITY;
    float sm0 = 0.f, sm1 = 0.f, sm2 = 0.f, sm3 = 0.f;
    for (int n = w; n < NNODE; n += 16) {
        float g = sgate[n];
        int se = ssel[n];
        float* r = hb + n * 128;
        float v0 = r[lane] * g;
        float v1 = r[lane + 32] * g;
        float v2 = r[lane + 64] * g;
        float v3 = r[lane + 96] * g;
        if (LAYER == 1) {
            r[lane] = v0; r[lane + 32] = v1; r[lane + 64] = v2; r[lane + 96] = v3;
        }
        if (se) {
            mx0 = fmaxf(mx0, v0); mx1 = fmaxf(mx1, v1);
            mx2 = fmaxf(mx2, v2); mx3 = fmaxf(mx3, v3);
        }
        sm0 += v0; sm1 += v1; sm2 += v2; sm3 += v3;
    }
    rmax[w * 128 + lane]      = mx0;
    rmax[w * 128 + lane + 32] = mx1;
    rmax[w * 128 + lane + 64] = mx2;
    rmax[w * 128 + lane + 96] = mx3;
    rsum[w * 128 + lane]      = sm0;
    rsum[w * 128 + lane + 32] = sm1;
    rsum[w * 128 + lane + 64] = sm2;
    rsum[w * 128 + lane + 96] = sm3;
    __syncthreads();
    if (tid < 128) {
        float M = -INFINITY, S = 0.f;
#pragma unroll
        for (int i = 0; i < 16; ++i) {
            M = fmaxf(M, rmax[i * 128 + tid]);
            S += rsum[i * 128 + tid];
        }
        xout[b * 256 + tid] = M;
        xout[b * 256 + 128 + tid] = S / (float)KK;
    }
}

// ---------------- MLP head ----------------
__global__ void __launch_bounds__(128)
head_kernel(const float* __restrict__ lw1, const float* __restrict__ lb1,
            const float* __restrict__ lw2, const float* __restrict__ lb2,
            const float* __restrict__ lw3, const float* __restrict__ lb3,
            float* __restrict__ out) {
    int b = blockIdx.x;
    int tid = threadIdx.x;   // 128
    __shared__ float z[256], z1[128], z2[64];
    z[tid]       = g_x1[b * 256 + tid]       + g_x2[b * 256 + tid];
    z[tid + 128] = g_x1[b * 256 + 128 + tid] + g_x2[b * 256 + 128 + tid];
    __syncthreads();
    float a = lb1[tid];
#pragma unroll 8
    for (int i = 0; i < 256; ++i) a += z[i] * lw1[i * 128 + tid];
    z1[tid] = fmaxf(a, 0.f);
    __syncthreads();
    if (tid < 64) {
        float a2 = lb2[tid];
#pragma unroll 8
        for (int i = 0; i < 128; ++i) a2 += z1[i] * lw2[i * 64 + tid];
        z2[tid] = fmaxf(a2, 0.f);
    }
    __syncthreads();
    if (tid == 0) {
        float a3 = lb3[0];
#pragma unroll 8
        for (int i = 0; i < 64; ++i) a3 += z2[i] * lw3[i];
        out[b] = 1.f / (1.f + expf(-a3));
    }
}

// ---------------- launch ----------------
extern "C" void kernel_launch(void* const* d_in, const int* in_sizes, int n_in,
                              void* d_out, int out_size) {
    const float* x   = (const float*)d_in[0];
    const int*   ei  = (const int*)d_in[1];
    const float* W1r = (const float*)d_in[2];
    const float* W1n = (const float*)d_in[3];
    const float* b1  = (const float*)d_in[4];
    const float* p1  = (const float*)d_in[5];
    const float* W2r = (const float*)d_in[6];
    const float* W2n = (const float*)d_in[7];
    const float* b2  = (const float*)d_in[8];
    const float* p2  = (const float*)d_in[9];
    const float* lw1 = (const float*)d_in[10];
    const float* lb1 = (const float*)d_in[11];
    const float* lw2 = (const float*)d_in[12];
    const float* lb2 = (const float*)d_in[13];
    const float* lw3 = (const float*)d_in[14];
    const float* lb3 = (const float*)d_in[15];
    float* out = (float*)d_out;

    const int* src = ei;
    const int* dst = ei + EDGES;

    // opt-in to >48KB dynamic smem for the staging agg kernel
    cudaFuncSetAttribute(agg_stage_kernel<1>,
                         cudaFuncAttributeMaxDynamicSharedMemorySize, AGG_SMEM_BYTES);
    cudaFuncSetAttribute(agg_stage_kernel<2>,
                         cudaFuncAttributeMaxDynamicSharedMemorySize, AGG_SMEM_BYTES);

    // edge buckets (edges are an input, rebuilt every call — stateless)
    zero_kernel<<<NN / 256, 256>>>();
    bucket_scatter_kernel<<<EDGES / 256, 256>>>(src, dst);

    dim3 agrid(4, BGRAPH);

    // conv1 + pool1
    agg_stage_kernel<1><<<agrid, 256, AGG_SMEM_BYTES>>>(x);
    conv_gemm_kernel<1><<<NN / 128, 256>>>(x, W1r, W1n, b1, p1);
    pool_kernel<1><<<BGRAPH, 512>>>();

    // conv2 + pool2 (on gated h)
    agg_stage_kernel<2><<<agrid, 256, AGG_SMEM_BYTES>>>(nullptr);
    conv_gemm_kernel<2><<<NN / 128, 256>>>(nullptr, W2r, W2n, b2, p2);
    pool_kernel<2><<<BGRAPH, 512>>>();

    // head
    head_kernel<<<BGRAPH, 128>>>(lw1, lb1, lw2, lb2, lw3, lb3, out);
}

// round 7
// speedup vs baseline: 1.2593x; 1.0931x over previous
#include <cuda_runtime.h>
#include <cuda_bf16.h>
#include <math.h>

// Problem constants
#define BGRAPH 128
#define NNODE  512
#define NN     (BGRAPH*NNODE)      // 65536
#define DFEAT  128
#define EDGES  524288
#define KEEP1  410
#define KEEP2  328
#define BUCKET_CAP 32

// ---------------- scratch (device globals; no runtime allocation) ----------------
__device__ float g_agg[NN*DFEAT];   // aggregated neighbor features
__device__ float g_h  [NN*DFEAT];   // conv1 output (gated in place by pool1)
__device__ float g_h2 [NN*DFEAT];   // conv2 output
__device__ float g_score[NN];       // node scores (written by GEMM epilogue)
__device__ int   g_deg[NN];
__device__ int   g_bucket[NN*BUCKET_CAP];
__device__ int   g_ovf_cnt;
__device__ int   g_ovf_d[EDGES];
__device__ int   g_ovf_s[EDGES];
__device__ unsigned char g_m1[NN];
__device__ float g_x1[BGRAPH*256];
__device__ float g_x2[BGRAPH*256];

// ---------------- packed fp32x2 helpers (Blackwell) ----------------
__device__ __forceinline__ unsigned long long pk2(float x) {
    unsigned long long d;
    asm("mov.b64 %0, {%1, %1};" : "=l"(d) : "f"(x));
    return d;
}
__device__ __forceinline__ unsigned long long ffma2(unsigned long long a,
                                                    unsigned long long b,
                                                    unsigned long long c) {
    unsigned long long d;
    asm("fma.rn.f32x2 %0, %1, %2, %3;" : "=l"(d) : "l"(a), "l"(b), "l"(c));
    return d;
}
__device__ __forceinline__ void unpk2(unsigned long long v, float& lo, float& hi) {
    asm("mov.b64 {%0, %1}, %2;" : "=f"(lo), "=f"(hi) : "l"(v));
}

// ---------------- bucketed edge build ----------------
__global__ void zero_kernel() {
    int i = blockIdx.x * blockDim.x + threadIdx.x;
    if (i < NN) g_deg[i] = 0;
    if (i == 0) g_ovf_cnt = 0;
}

__global__ void bucket_scatter_kernel(const int* __restrict__ src,
                                      const int* __restrict__ dst) {
    int i = blockIdx.x * blockDim.x + threadIdx.x;
    if (i < EDGES) {
        int d = dst[i];
        int s = src[i];
        int pos = atomicAdd(&g_deg[d], 1);
        if (pos < BUCKET_CAP) {
            g_bucket[d * BUCKET_CAP + pos] = s;
        } else {
            int o = atomicAdd(&g_ovf_cnt, 1);
            g_ovf_d[o] = d;
            g_ovf_s[o] = s;
        }
    }
}

// ---------------- neighbor aggregation: warp/node, bucket idx, MLP=8 ----------------
template<int LAYER>
__global__ void __launch_bounds__(256)
agg_gather_kernel(const float* __restrict__ xin) {
    const float* feat = (LAYER == 1) ? xin : g_h;
    int gw = (blockIdx.x * blockDim.x + threadIdx.x) >> 5;
    int lane = threadIdx.x & 31;
    if (gw >= NN) return;

    int nv = __ldg(&g_deg[gw]);
    int m = min(nv, BUCKET_CAP);
    int idx = 0;
    if (lane < m) idx = __ldg(&g_bucket[gw * BUCKET_CAP + lane]);

    const float4* f4 = (const float4*)feat;
    float a0 = 0.f, a1 = 0.f, a2 = 0.f, a3 = 0.f;
    int e = 0;
    for (; e + 8 <= m; e += 8) {
        int i0 = __shfl_sync(0xffffffffu, idx, e);
        int i1 = __shfl_sync(0xffffffffu, idx, e + 1);
        int i2 = __shfl_sync(0xffffffffu, idx, e + 2);
        int i3 = __shfl_sync(0xffffffffu, idx, e + 3);
        int i4 = __shfl_sync(0xffffffffu, idx, e + 4);
        int i5 = __shfl_sync(0xffffffffu, idx, e + 5);
        int i6 = __shfl_sync(0xffffffffu, idx, e + 6);
        int i7 = __shfl_sync(0xffffffffu, idx, e + 7);
        float4 v0 = __ldg(f4 + (size_t)i0 * 32 + lane);
        float4 v1 = __ldg(f4 + (size_t)i1 * 32 + lane);
        float4 v2 = __ldg(f4 + (size_t)i2 * 32 + lane);
        float4 v3 = __ldg(f4 + (size_t)i3 * 32 + lane);
        float4 v4 = __ldg(f4 + (size_t)i4 * 32 + lane);
        float4 v5 = __ldg(f4 + (size_t)i5 * 32 + lane);
        float4 v6 = __ldg(f4 + (size_t)i6 * 32 + lane);
        float4 v7 = __ldg(f4 + (size_t)i7 * 32 + lane);
        a0 += ((v0.x + v1.x) + (v2.x + v3.x)) + ((v4.x + v5.x) + (v6.x + v7.x));
        a1 += ((v0.y + v1.y) + (v2.y + v3.y)) + ((v4.y + v5.y) + (v6.y + v7.y));
        a2 += ((v0.z + v1.z) + (v2.z + v3.z)) + ((v4.z + v5.z) + (v6.z + v7.z));
        a3 += ((v0.w + v1.w) + (v2.w + v3.w)) + ((v4.w + v5.w) + (v6.w + v7.w));
    }
    for (; e + 4 <= m; e += 4) {
        int i0 = __shfl_sync(0xffffffffu, idx, e);
        int i1 = __shfl_sync(0xffffffffu, idx, e + 1);
        int i2 = __shfl_sync(0xffffffffu, idx, e + 2);
        int i3 = __shfl_sync(0xffffffffu, idx, e + 3);
        float4 v0 = __ldg(f4 + (size_t)i0 * 32 + lane);
        float4 v1 = __ldg(f4 + (size_t)i1 * 32 + lane);
        float4 v2 = __ldg(f4 + (size_t)i2 * 32 + lane);
        float4 v3 = __ldg(f4 + (size_t)i3 * 32 + lane);
        a0 += (v0.x + v1.x) + (v2.x + v3.x);
        a1 += (v0.y + v1.y) + (v2.y + v3.y);
        a2 += (v0.z + v1.z) + (v2.z + v3.z);
        a3 += (v0.w + v1.w) + (v2.w + v3.w);
    }
    for (; e < m; ++e) {
        int i0 = __shfl_sync(0xffffffffu, idx, e);
        float4 v0 = __ldg(f4 + (size_t)i0 * 32 + lane);
        a0 += v0.x; a1 += v0.y; a2 += v0.z; a3 += v0.w;
    }
    if (nv > BUCKET_CAP) {   // correctness fallback; ~never taken
        int oc = g_ovf_cnt;
        for (int t = 0; t < oc; ++t) {
            if (g_ovf_d[t] == gw) {
                float4 v0 = __ldg(f4 + (size_t)g_ovf_s[t] * 32 + lane);
                a0 += v0.x; a1 += v0.y; a2 += v0.z; a3 += v0.w;
            }
        }
    }
    ((float4*)g_agg)[(size_t)gw * 32 + lane] = make_float4(a0, a1, a2, a3);
}

// ---------------- conv GEMM: out = relu(A1@Wr + A2@Wn + b); score epilogue ----
// Tile 128x128, K=256, 256 threads, f32x2 packed FMA, double-buffered smem
// (one barrier per chunk).
template<int LAYER>
__global__ void __launch_bounds__(256, 2)
conv_gemm_kernel(const float* __restrict__ A1in,
                 const float* __restrict__ Wr,
                 const float* __restrict__ Wn,
                 const float* __restrict__ bias,
                 const float* __restrict__ p) {
    const float* A1 = (LAYER == 1) ? A1in : g_h;
    const float* A2 = g_agg;
    float* Out = (LAYER == 1) ? g_h : g_h2;

    __shared__ float As[2][8][128];
    __shared__ float Ws[2][8][128];

    int tid = threadIdx.x;
    int cx = tid & 31;        // column group: cols cx + 32*j
    int ry = tid >> 5;        // row group: rows ry*16 .. ry*16+15 (8 pairs)
    int row0 = blockIdx.x * 128;
    int lrow = tid >> 1;              // A loader row 0..127
    int lk4 = (tid & 1) * 4;          // A loader k sub-offset

    unsigned long long acc[8][4];
#pragma unroll
    for (int r = 0; r < 8; ++r)
#pragma unroll
        for (int j = 0; j < 4; ++j) acc[r][j] = 0ull;

    // preload chunk 0 into buffer 0
    {
        float4 av = *(const float4*)&A1[(size_t)(row0 + lrow) * 128 + lk4];
        float4 wv = *(const float4*)&Wr[(size_t)ry * 128 + cx * 4];
        As[0][lk4 + 0][lrow] = av.x;
        As[0][lk4 + 1][lrow] = av.y;
        As[0][lk4 + 2][lrow] = av.z;
        As[0][lk4 + 3][lrow] = av.w;
        *(float4*)&Ws[0][ry][cx * 4] = wv;
    }
    __syncthreads();

#pragma unroll 1
    for (int chunk = 0; chunk < 32; ++chunk) {
        int cur = chunk & 1;

        // prefetch next chunk into registers
        float4 nav, nwv;
        bool hasNext = (chunk + 1) < 32;
        if (hasNext) {
            int nc = chunk + 1;
            const float* A = (nc < 16) ? A1 : A2;
            const float* W = (nc < 16) ? Wr : Wn;
            int k0n = (nc & 15) * 8;
            nav = *(const float4*)&A[(size_t)(row0 + lrow) * 128 + k0n + lk4];
            nwv = *(const float4*)&W[(size_t)(k0n + ry) * 128 + cx * 4];
        }

        // compute on current buffer
#pragma unroll
        for (int k = 0; k < 8; ++k) {
            unsigned long long ap[8];
#pragma unroll
            for (int r = 0; r < 8; ++r)
                ap[r] = *(const unsigned long long*)&As[cur][k][ry * 16 + 2 * r];
#pragma unroll
            for (int j = 0; j < 4; ++j) {
                unsigned long long wp = pk2(Ws[cur][k][cx + 32 * j]);
#pragma unroll
                for (int r = 0; r < 8; ++r)
                    acc[r][j] = ffma2(ap[r], wp, acc[r][j]);
            }
        }

        // store prefetched chunk into the other buffer
        if (hasNext) {
            int nxt = cur ^ 1;
            As[nxt][lk4 + 0][lrow] = nav.x;
            As[nxt][lk4 + 1][lrow] = nav.y;
            As[nxt][lk4 + 2][lrow] = nav.z;
            As[nxt][lk4 + 3][lrow] = nav.w;
            *(float4*)&Ws[nxt][ry][cx * 4] = nwv;
            __syncthreads();
        }
    }

    // ---- epilogue: bias + relu + per-row score (h . p / ||p||) ----
    float pv[4];
    float pn = 0.f;
#pragma unroll
    for (int j = 0; j < 4; ++j) {
        pv[j] = __ldg(&p[cx + 32 * j]);
        pn += pv[j] * pv[j];
    }
#pragma unroll
    for (int o = 16; o; o >>= 1) pn += __shfl_xor_sync(0xffffffffu, pn, o);
    float pinv = rsqrtf(pn);

#pragma unroll
    for (int r = 0; r < 8; ++r) {
        float slo = 0.f, shi = 0.f;
        int row = row0 + ry * 16 + 2 * r;
#pragma unroll
        for (int j = 0; j < 4; ++j) {
            int col = cx + 32 * j;
            float bb = __ldg(&bias[col]);
            float lo, hi;
            unpk2(acc[r][j], lo, hi);
            lo = fmaxf(lo + bb, 0.f);
            hi = fmaxf(hi + bb, 0.f);
            Out[(size_t)row * 128 + col]       = lo;
            Out[(size_t)(row + 1) * 128 + col] = hi;
            slo += lo * pv[j];
            shi += hi * pv[j];
        }
#pragma unroll
        for (int o = 16; o; o >>= 1) {
            slo += __shfl_xor_sync(0xffffffffu, slo, o);
            shi += __shfl_xor_sync(0xffffffffu, shi, o);
        }
        if (cx == 0) {
            g_score[row]     = slo * pinv;
            g_score[row + 1] = shi * pinv;
        }
    }
}

// ---------------- pool: topk + gate + readout (one block per graph) ----------------
template<int LAYER>
__global__ void __launch_bounds__(512)
pool_kernel() {
    constexpr int KK = (LAYER == 1) ? KEEP1 : KEEP2;
    float* h = (LAYER == 1) ? g_h : g_h2;
    float* xout = (LAYER == 1) ? g_x1 : g_x2;

    int b = blockIdx.x;
    int tid = threadIdx.x;
    int lane = tid & 31, w = tid >> 5;   // 16 warps

    __shared__ float sval[512];
    __shared__ float ssort[512];
    __shared__ float sgate[512];
    __shared__ int   ssel[512];
    __shared__ int   sscan[512];
    __shared__ float rmax[16 * 128];
    __shared__ float rsum[16 * 128];

    float* hb = h + (size_t)b * NNODE * 128;

    // scores: precomputed by GEMM epilogue
    {
        float s = g_score[b * NNODE + tid];
        if (LAYER == 2 && !g_m1[b * NNODE + tid]) s = -INFINITY;
        sval[tid] = s;
        ssort[tid] = s;
    }
    __syncthreads();

    // bitonic sort (descending) to find threshold = K-th largest
    for (int k2 = 2; k2 <= 512; k2 <<= 1) {
        for (int j = k2 >> 1; j > 0; j >>= 1) {
            int ixj = tid ^ j;
            float a = ssort[tid];
            float bv = ssort[ixj];
            bool desc = ((tid & k2) == 0);
            bool isLower = (tid < ixj);
            float res = (desc == isLower) ? fmaxf(a, bv) : fminf(a, bv);
            __syncthreads();
            ssort[tid] = res;
            __syncthreads();
        }
    }
    float t = ssort[KK - 1];

    // exact selection with lowest-index tie-break (matches lax.top_k)
    float s = sval[tid];
    int fgt = (s > t) ? 1 : 0;
    int feq = (s == t) ? 1 : 0;
    sscan[tid] = (fgt << 16) | feq;
    __syncthreads();
    for (int off = 1; off < 512; off <<= 1) {
        int v = (tid >= off) ? sscan[tid - off] : 0;
        __syncthreads();
        sscan[tid] += v;
        __syncthreads();
    }
    int totgt = sscan[511] >> 16;
    int preeq = (sscan[tid] & 0xffff) - feq;
    int sel = fgt | (feq && (preeq < KK - totgt));
    ssel[tid] = sel;
    sgate[tid] = sel ? tanhf(s) : 0.f;
    if (LAYER == 1) g_m1[b * NNODE + tid] = (unsigned char)sel;
    __syncthreads();

    // gate (+writeback for layer1) + readout (max & mean over kept nodes)
    float mx0 = -INFINITY, mx1 = -INFINITY, mx2 = -INFINITY, mx3 = -INFINITY;
    float sm0 = 0.f, sm1 = 0.f, sm2 = 0.f, sm3 = 0.f;
    for (int n = w; n < NNODE; n += 16) {
        float g = sgate[n];
        int se = ssel[n];
        float* r = hb + n * 128;
        float v0 = r[lane] * g;
        float v1 = r[lane + 32] * g;
        float v2 = r[lane + 64] * g;
        float v3 = r[lane + 96] * g;
        if (LAYER == 1) {
            r[lane] = v0; r[lane + 32] = v1; r[lane + 64] = v2; r[lane + 96] = v3;
        }
        if (se) {
            mx0 = fmaxf(mx0, v0); mx1 = fmaxf(mx1, v1);
            mx2 = fmaxf(mx2, v2); mx3 = fmaxf(mx3, v3);
        }
        sm0 += v0; sm1 += v1; sm2 += v2; sm3 += v3;
    }
    rmax[w * 128 + lane]      = mx0;
    rmax[w * 128 + lane + 32] = mx1;
    rmax[w * 128 + lane + 64] = mx2;
    rmax[w * 128 + lane + 96] = mx3;
    rsum[w * 128 + lane]      = sm0;
    rsum[w * 128 + lane + 32] = sm1;
    rsum[w * 128 + lane + 64] = sm2;
    rsum[w * 128 + lane + 96] = sm3;
    __syncthreads();
    if (tid < 128) {
        float M = -INFINITY, S = 0.f;
#pragma unroll
        for (int i = 0; i < 16; ++i) {
            M = fmaxf(M, rmax[i * 128 + tid]);
            S += rsum[i * 128 + tid];
        }
        xout[b * 256 + tid] = M;
        xout[b * 256 + 128 + tid] = S / (float)KK;
    }
}

// ---------------- MLP head ----------------
__global__ void __launch_bounds__(128)
head_kernel(const float* __restrict__ lw1, const float* __restrict__ lb1,
            const float* __restrict__ lw2, const float* __restrict__ lb2,
            const float* __restrict__ lw3, const float* __restrict__ lb3,
            float* __restrict__ out) {
    int b = blockIdx.x;
    int tid = threadIdx.x;   // 128
    __shared__ float z[256], z1[128], z2[64];
    z[tid]       = g_x1[b * 256 + tid]       + g_x2[b * 256 + tid];
    z[tid + 128] = g_x1[b * 256 + 128 + tid] + g_x2[b * 256 + 128 + tid];
    __syncthreads();
    float a = lb1[tid];
#pragma unroll 8
    for (int i = 0; i < 256; ++i) a += z[i] * lw1[i * 128 + tid];
    z1[tid] = fmaxf(a, 0.f);
    __syncthreads();
    if (tid < 64) {
        float a2 = lb2[tid];
#pragma unroll 8
        for (int i = 0; i < 128; ++i) a2 += z1[i] * lw2[i * 64 + tid];
        z2[tid] = fmaxf(a2, 0.f);
    }
    __syncthreads();
    if (tid == 0) {
        float a3 = lb3[0];
#pragma unroll 8
        for (int i = 0; i < 64; ++i) a3 += z2[i] * lw3[i];
        out[b] = 1.f / (1.f + expf(-a3));
    }
}

// ---------------- launch ----------------
extern "C" void kernel_launch(void* const* d_in, const int* in_sizes, int n_in,
                              void* d_out, int out_size) {
    const float* x   = (const float*)d_in[0];
    const int*   ei  = (const int*)d_in[1];
    const float* W1r = (const float*)d_in[2];
    const float* W1n = (const float*)d_in[3];
    const float* b1  = (const float*)d_in[4];
    const float* p1  = (const float*)d_in[5];
    const float* W2r = (const float*)d_in[6];
    const float* W2n = (const float*)d_in[7];
    const float* b2  = (const float*)d_in[8];
    const float* p2  = (const float*)d_in[9];
    const float* lw1 = (const float*)d_in[10];
    const float* lb1 = (const float*)d_in[11];
    const float* lw2 = (const float*)d_in[12];
    const float* lb2 = (const float*)d_in[13];
    const float* lw3 = (const float*)d_in[14];
    const float* lb3 = (const float*)d_in[15];
    float* out = (float*)d_out;

    const int* src = ei;
    const int* dst = ei + EDGES;

    // edge buckets (edges are an input, rebuilt every call — stateless)
    zero_kernel<<<NN / 256, 256>>>();
    bucket_scatter_kernel<<<EDGES / 256, 256>>>(src, dst);

    // conv1 + pool1
    agg_gather_kernel<1><<<NN * 32 / 256, 256>>>(x);
    conv_gemm_kernel<1><<<NN / 128, 256>>>(x, W1r, W1n, b1, p1);
    pool_kernel<1><<<BGRAPH, 512>>>();

    // conv2 + pool2 (on gated h)
    agg_gather_kernel<2><<<NN * 32 / 256, 256>>>(nullptr);
    conv_gemm_kernel<2><<<NN / 128, 256>>>(nullptr, W2r, W2n, b2, p2);
    pool_kernel<2><<<BGRAPH, 512>>>();

    // head
    head_kernel<<<BGRAPH, 128>>>(lw1, lb1, lw2, lb2, lw3, lb3, out);
}

// round 8
// speedup vs baseline: 1.7441x; 1.3849x over previous
#include <cuda_runtime.h>
#include <cuda_bf16.h>
#include <math.h>

// Problem constants
#define BGRAPH 128
#define NNODE  512
#define NN     (BGRAPH*NNODE)      // 65536
#define DFEAT  128
#define EDGES  524288
#define KEEP1  410
#define KEEP2  328
#define BUCKET_CAP 32

// ---------------- scratch (device globals; no runtime allocation) ----------------
__device__ float g_agg[NN*DFEAT];   // aggregated neighbor features
__device__ float g_h  [NN*DFEAT];   // conv1 output (gated in place by pool1)
__device__ float g_h2 [NN*DFEAT];   // conv2 output
__device__ float g_score[NN];       // node scores (written by GEMM epilogue)
__device__ int   g_deg[NN];
__device__ int   g_bucket[NN*BUCKET_CAP];
__device__ int   g_ovf_cnt;
__device__ int   g_ovf_d[EDGES];
__device__ int   g_ovf_s[EDGES];
__device__ unsigned char g_m1[NN];
__device__ float g_x1[BGRAPH*256];
__device__ float g_x2[BGRAPH*256];

// ---------------- packed fp32x2 helpers (Blackwell) ----------------
__device__ __forceinline__ unsigned long long pk2(float x) {
    unsigned long long d;
    asm("mov.b64 %0, {%1, %1};" : "=l"(d) : "f"(x));
    return d;
}
__device__ __forceinline__ unsigned long long ffma2(unsigned long long a,
                                                    unsigned long long b,
                                                    unsigned long long c) {
    unsigned long long d;
    asm("fma.rn.f32x2 %0, %1, %2, %3;" : "=l"(d) : "l"(a), "l"(b), "l"(c));
    return d;
}
__device__ __forceinline__ void unpk2(unsigned long long v, float& lo, float& hi) {
    asm("mov.b64 {%0, %1}, %2;" : "=f"(lo), "=f"(hi) : "l"(v));
}

// ---------------- bucketed edge build ----------------
__global__ void zero_kernel() {
    int i = blockIdx.x * blockDim.x + threadIdx.x;
    if (i < NN) g_deg[i] = 0;
    if (i == 0) g_ovf_cnt = 0;
}

__global__ void bucket_scatter_kernel(const int* __restrict__ src,
                                      const int* __restrict__ dst) {
    int i = blockIdx.x * blockDim.x + threadIdx.x;
    if (i < EDGES) {
        int d = dst[i];
        int s = src[i];
        int pos = atomicAdd(&g_deg[d], 1);
        if (pos < BUCKET_CAP) {
            g_bucket[d * BUCKET_CAP + pos] = s;
        } else {
            int o = atomicAdd(&g_ovf_cnt, 1);
            g_ovf_d[o] = d;
            g_ovf_s[o] = s;
        }
    }
}

// ---------------- neighbor aggregation: warp/node, bucket idx, MLP=8 ----------------
template<int LAYER>
__global__ void __launch_bounds__(256)
agg_gather_kernel(const float* __restrict__ xin) {
    const float* feat = (LAYER == 1) ? xin : g_h;
    int gw = (blockIdx.x * blockDim.x + threadIdx.x) >> 5;
    int lane = threadIdx.x & 31;
    if (gw >= NN) return;

    int nv = __ldg(&g_deg[gw]);
    int m = min(nv, BUCKET_CAP);
    int idx = 0;
    if (lane < m) idx = __ldg(&g_bucket[gw * BUCKET_CAP + lane]);

    const float4* f4 = (const float4*)feat;
    float a0 = 0.f, a1 = 0.f, a2 = 0.f, a3 = 0.f;
    int e = 0;
    for (; e + 8 <= m; e += 8) {
        int i0 = __shfl_sync(0xffffffffu, idx, e);
        int i1 = __shfl_sync(0xffffffffu, idx, e + 1);
        int i2 = __shfl_sync(0xffffffffu, idx, e + 2);
        int i3 = __shfl_sync(0xffffffffu, idx, e + 3);
        int i4 = __shfl_sync(0xffffffffu, idx, e + 4);
        int i5 = __shfl_sync(0xffffffffu, idx, e + 5);
        int i6 = __shfl_sync(0xffffffffu, idx, e + 6);
        int i7 = __shfl_sync(0xffffffffu, idx, e + 7);
        float4 v0 = __ldg(f4 + (size_t)i0 * 32 + lane);
        float4 v1 = __ldg(f4 + (size_t)i1 * 32 + lane);
        float4 v2 = __ldg(f4 + (size_t)i2 * 32 + lane);
        float4 v3 = __ldg(f4 + (size_t)i3 * 32 + lane);
        float4 v4 = __ldg(f4 + (size_t)i4 * 32 + lane);
        float4 v5 = __ldg(f4 + (size_t)i5 * 32 + lane);
        float4 v6 = __ldg(f4 + (size_t)i6 * 32 + lane);
        float4 v7 = __ldg(f4 + (size_t)i7 * 32 + lane);
        a0 += ((v0.x + v1.x) + (v2.x + v3.x)) + ((v4.x + v5.x) + (v6.x + v7.x));
        a1 += ((v0.y + v1.y) + (v2.y + v3.y)) + ((v4.y + v5.y) + (v6.y + v7.y));
        a2 += ((v0.z + v1.z) + (v2.z + v3.z)) + ((v4.z + v5.z) + (v6.z + v7.z));
        a3 += ((v0.w + v1.w) + (v2.w + v3.w)) + ((v4.w + v5.w) + (v6.w + v7.w));
    }
    for (; e + 4 <= m; e += 4) {
        int i0 = __shfl_sync(0xffffffffu, idx, e);
        int i1 = __shfl_sync(0xffffffffu, idx, e + 1);
        int i2 = __shfl_sync(0xffffffffu, idx, e + 2);
        int i3 = __shfl_sync(0xffffffffu, idx, e + 3);
        float4 v0 = __ldg(f4 + (size_t)i0 * 32 + lane);
        float4 v1 = __ldg(f4 + (size_t)i1 * 32 + lane);
        float4 v2 = __ldg(f4 + (size_t)i2 * 32 + lane);
        float4 v3 = __ldg(f4 + (size_t)i3 * 32 + lane);
        a0 += (v0.x + v1.x) + (v2.x + v3.x);
        a1 += (v0.y + v1.y) + (v2.y + v3.y);
        a2 += (v0.z + v1.z) + (v2.z + v3.z);
        a3 += (v0.w + v1.w) + (v2.w + v3.w);
    }
    for (; e < m; ++e) {
        int i0 = __shfl_sync(0xffffffffu, idx, e);
        float4 v0 = __ldg(f4 + (size_t)i0 * 32 + lane);
        a0 += v0.x; a1 += v0.y; a2 += v0.z; a3 += v0.w;
    }
    if (nv > BUCKET_CAP) {   // correctness fallback; ~never taken
        int oc = g_ovf_cnt;
        for (int t = 0; t < oc; ++t) {
            if (g_ovf_d[t] == gw) {
                float4 v0 = __ldg(f4 + (size_t)g_ovf_s[t] * 32 + lane);
                a0 += v0.x; a1 += v0.y; a2 += v0.z; a3 += v0.w;
            }
        }
    }
    ((float4*)g_agg)[(size_t)gw * 32 + lane] = make_float4(a0, a1, a2, a3);
}

// ---------------- conv GEMM: out = relu(A1@Wr + A2@Wn + b); score epilogue ----
// Tile 128x128, K=256 (two 128 sources), 256 threads, f32x2 packed FMA.
// Single-buffer staging (round-6 proven: 118.6us).
template<int LAYER>
__global__ void __launch_bounds__(256, 2)
conv_gemm_kernel(const float* __restrict__ A1in,
                 const float* __restrict__ Wr,
                 const float* __restrict__ Wn,
                 const float* __restrict__ bias,
                 const float* __restrict__ p) {
    const float* A1 = (LAYER == 1) ? A1in : g_h;
    const float* A2 = g_agg;
    float* Out = (LAYER == 1) ? g_h : g_h2;

    __shared__ float As[8][128];
    __shared__ float Ws[8][128];

    int tid = threadIdx.x;
    int cx = tid & 31;        // column group: cols cx + 32*j
    int ry = tid >> 5;        // row group: rows ry*16 .. ry*16+15 (8 pairs)
    int row0 = blockIdx.x * 128;
    int lrow = tid >> 1;              // A loader row 0..127
    int lk4 = (tid & 1) * 4;          // A loader k sub-offset

    unsigned long long acc[8][4];
#pragma unroll
    for (int r = 0; r < 8; ++r)
#pragma unroll
        for (int j = 0; j < 4; ++j) acc[r][j] = 0ull;

#pragma unroll 1
    for (int chunk = 0; chunk < 32; ++chunk) {
        const float* A = (chunk < 16) ? A1 : A2;
        const float* W = (chunk < 16) ? Wr : Wn;
        int k0 = (chunk & 15) * 8;

        float4 av = *(const float4*)&A[(size_t)(row0 + lrow) * 128 + k0 + lk4];
        float4 wv = *(const float4*)&W[(size_t)(k0 + ry) * 128 + cx * 4];

        __syncthreads();   // previous iteration's reads done
        As[lk4 + 0][lrow] = av.x;
        As[lk4 + 1][lrow] = av.y;
        As[lk4 + 2][lrow] = av.z;
        As[lk4 + 3][lrow] = av.w;
        *(float4*)&Ws[ry][cx * 4] = wv;
        __syncthreads();

#pragma unroll
        for (int k = 0; k < 8; ++k) {
            unsigned long long ap[8];
#pragma unroll
            for (int r = 0; r < 8; ++r)
                ap[r] = *(const unsigned long long*)&As[k][ry * 16 + 2 * r];
#pragma unroll
            for (int j = 0; j < 4; ++j) {
                unsigned long long wp = pk2(Ws[k][cx + 32 * j]);
#pragma unroll
                for (int r = 0; r < 8; ++r)
                    acc[r][j] = ffma2(ap[r], wp, acc[r][j]);
            }
        }
    }

    // ---- epilogue: bias + relu + per-row score (h . p / ||p||) ----
    float pv[4];
    float pn = 0.f;
#pragma unroll
    for (int j = 0; j < 4; ++j) {
        pv[j] = __ldg(&p[cx + 32 * j]);
        pn += pv[j] * pv[j];
    }
#pragma unroll
    for (int o = 16; o; o >>= 1) pn += __shfl_xor_sync(0xffffffffu, pn, o);
    float pinv = rsqrtf(pn);

#pragma unroll
    for (int r = 0; r < 8; ++r) {
        float slo = 0.f, shi = 0.f;
        int row = row0 + ry * 16 + 2 * r;
#pragma unroll
        for (int j = 0; j < 4; ++j) {
            int col = cx + 32 * j;
            float bb = __ldg(&bias[col]);
            float lo, hi;
            unpk2(acc[r][j], lo, hi);
            lo = fmaxf(lo + bb, 0.f);
            hi = fmaxf(hi + bb, 0.f);
            Out[(size_t)row * 128 + col]       = lo;
            Out[(size_t)(row + 1) * 128 + col] = hi;
            slo += lo * pv[j];
            shi += hi * pv[j];
        }
#pragma unroll
        for (int o = 16; o; o >>= 1) {
            slo += __shfl_xor_sync(0xffffffffu, slo, o);
            shi += __shfl_xor_sync(0xffffffffu, shi, o);
        }
        if (cx == 0) {
            g_score[row]     = slo * pinv;
            g_score[row + 1] = shi * pinv;
        }
    }
}

// ---------------- pool: topk + gate + readout (one block per graph) ----------------
template<int LAYER>
__global__ void __launch_bounds__(512)
pool_kernel() {
    constexpr int KK = (LAYER == 1) ? KEEP1 : KEEP2;
    float* h = (LAYER == 1) ? g_h : g_h2;
    float* xout = (LAYER == 1) ? g_x1 : g_x2;

    int b = blockIdx.x;
    int tid = threadIdx.x;
    int lane = tid & 31, w = tid >> 5;   // 16 warps

    __shared__ float sval[512];
    __shared__ float ssort[512];
    __shared__ float sgate[512];
    __shared__ int   ssel[512];
    __shared__ int   sscan[512];
    __shared__ float rmax[16 * 128];
    __shared__ float rsum[16 * 128];

    float* hb = h + (size_t)b * NNODE * 128;

    // scores: precomputed by GEMM epilogue
    {
        float s = g_score[b * NNODE + tid];
        if (LAYER == 2 && !g_m1[b * NNODE + tid]) s = -INFINITY;
        sval[tid] = s;
        ssort[tid] = s;
    }
    __syncthreads();

    // bitonic sort (descending) to find threshold = K-th largest
    for (int k2 = 2; k2 <= 512; k2 <<= 1) {
        for (int j = k2 >> 1; j > 0; j >>= 1) {
            int ixj = tid ^ j;
            float a = ssort[tid];
            float bv = ssort[ixj];
            bool desc = ((tid & k2) == 0);
            bool isLower = (tid < ixj);
            float res = (desc == isLower) ? fmaxf(a, bv) : fminf(a, bv);
            __syncthreads();
            ssort[tid] = res;
            __syncthreads();
        }
    }
    float t = ssort[KK - 1];

    // exact selection with lowest-index tie-break (matches lax.top_k)
    float s = sval[tid];
    int fgt = (s > t) ? 1 : 0;
    int feq = (s == t) ? 1 : 0;
    sscan[tid] = (fgt << 16) | feq;
    __syncthreads();
    for (int off = 1; off < 512; off <<= 1) {
        int v = (tid >= off) ? sscan[tid - off] : 0;
        __syncthreads();
        sscan[tid] += v;
        __syncthreads();
    }
    int totgt = sscan[511] >> 16;
    int preeq = (sscan[tid] & 0xffff) - feq;
    int sel = fgt | (feq && (preeq < KK - totgt));
    ssel[tid] = sel;
    sgate[tid] = sel ? tanhf(s) : 0.f;
    if (LAYER == 1) g_m1[b * NNODE + tid] = (unsigned char)sel;
    __syncthreads();

    // gate (+writeback for layer1) + readout (max & mean over kept nodes)
    float mx0 = -INFINITY, mx1 = -INFINITY, mx2 = -INFINITY, mx3 = -INFINITY;
    float sm0 = 0.f, sm1 = 0.f, sm2 = 0.f, sm3 = 0.f;
    for (int n = w; n < NNODE; n += 16) {
        float g = sgate[n];
        int se = ssel[n];
        float* r = hb + n * 128;
        float v0 = r[lane] * g;
        float v1 = r[lane + 32] * g;
        float v2 = r[lane + 64] * g;
        float v3 = r[lane + 96] * g;
        if (LAYER == 1) {
            r[lane] = v0; r[lane + 32] = v1; r[lane + 64] = v2; r[lane + 96] = v3;
        }
        if (se) {
            mx0 = fmaxf(mx0, v0); mx1 = fmaxf(mx1, v1);
            mx2 = fmaxf(mx2, v2); mx3 = fmaxf(mx3, v3);
        }
        sm0 += v0; sm1 += v1; sm2 += v2; sm3 += v3;
    }
    rmax[w * 128 + lane]      = mx0;
    rmax[w * 128 + lane + 32] = mx1;
    rmax[w * 128 + lane + 64] = mx2;
    rmax[w * 128 + lane + 96] = mx3;
    rsum[w * 128 + lane]      = sm0;
    rsum[w * 128 + lane + 32] = sm1;
    rsum[w * 128 + lane + 64] = sm2;
    rsum[w * 128 + lane + 96] = sm3;
    __syncthreads();
    if (tid < 128) {
        float M = -INFINITY, S = 0.f;
#pragma unroll
        for (int i = 0; i < 16; ++i) {
            M = fmaxf(M, rmax[i * 128 + tid]);
            S += rsum[i * 128 + tid];
        }
        xout[b * 256 + tid] = M;
        xout[b * 256 + 128 + tid] = S / (float)KK;
    }
}

// ---------------- MLP head ----------------
__global__ void __launch_bounds__(128)
head_kernel(const float* __restrict__ lw1, const float* __restrict__ lb1,
            const float* __restrict__ lw2, const float* __restrict__ lb2,
            const float* __restrict__ lw3, const float* __restrict__ lb3,
            float* __restrict__ out) {
    int b = blockIdx.x;
    int tid = threadIdx.x;   // 128
    __shared__ float z[256], z1[128], z2[64];
    z[tid]       = g_x1[b * 256 + tid]       + g_x2[b * 256 + tid];
    z[tid + 128] = g_x1[b * 256 + 128 + tid] + g_x2[b * 256 + 128 + tid];
    __syncthreads();
    float a = lb1[tid];
#pragma unroll 8
    for (int i = 0; i < 256; ++i) a += z[i] * lw1[i * 128 + tid];
    z1[tid] = fmaxf(a, 0.f);
    __syncthreads();
    if (tid < 64) {
        float a2 = lb2[tid];
#pragma unroll 8
        for (int i = 0; i < 128; ++i) a2 += z1[i] * lw2[i * 64 + tid];
        z2[tid] = fmaxf(a2, 0.f);
    }
    __syncthreads();
    if (tid == 0) {
        float a3 = lb3[0];
#pragma unroll 8
        for (int i = 0; i < 64; ++i) a3 += z2[i] * lw3[i];
        out[b] = 1.f / (1.f + expf(-a3));
    }
}

// ---------------- launch ----------------
extern "C" void kernel_launch(void* const* d_in, const int* in_sizes, int n_in,
                              void* d_out, int out_size) {
    const float* x   = (const float*)d_in[0];
    const int*   ei  = (const int*)d_in[1];
    const float* W1r = (const float*)d_in[2];
    const float* W1n = (const float*)d_in[3];
    const float* b1  = (const float*)d_in[4];
    const float* p1  = (const float*)d_in[5];
    const float* W2r = (const float*)d_in[6];
    const float* W2n = (const float*)d_in[7];
    const float* b2  = (const float*)d_in[8];
    const float* p2  = (const float*)d_in[9];
    const float* lw1 = (const float*)d_in[10];
    const float* lb1 = (const float*)d_in[11];
    const float* lw2 = (const float*)d_in[12];
    const float* lb2 = (const float*)d_in[13];
    const float* lw3 = (const float*)d_in[14];
    const float* lb3 = (const float*)d_in[15];
    float* out = (float*)d_out;

    const int* src = ei;
    const int* dst = ei + EDGES;

    // edge buckets (edges are an input, rebuilt every call — stateless)
    zero_kernel<<<NN / 256, 256>>>();
    bucket_scatter_kernel<<<EDGES / 256, 256>>>(src, dst);

    // conv1 + pool1
    agg_gather_kernel<1><<<NN * 32 / 256, 256>>>(x);
    conv_gemm_kernel<1><<<NN / 128, 256>>>(x, W1r, W1n, b1, p1);
    pool_kernel<1><<<BGRAPH, 512>>>();

    // conv2 + pool2 (on gated h)
    agg_gather_kernel<2><<<NN * 32 / 256, 256>>>(nullptr);
    conv_gemm_kernel<2><<<NN / 128, 256>>>(nullptr, W2r, W2n, b2, p2);
    pool_kernel<2><<<BGRAPH, 512>>>();

    // head
    head_kernel<<<BGRAPH, 128>>>(lw1, lb1, lw2, lb2, lw3, lb3, out);
}

// round 10
// speedup vs baseline: 1.9633x; 1.1257x over previous
#include <cuda_runtime.h>
#include <cuda_bf16.h>
#include <math.h>

// Problem constants
#define BGRAPH 128
#define NNODE  512
#define NN     (BGRAPH*NNODE)      // 65536
#define DFEAT  128
#define EDGES  524288
#define KEEP1  410
#define KEEP2  328
#define BUCKET_CAP 32

// ---------------- scratch (device globals; no runtime allocation) ----------------
__device__ float g_agg[NN*DFEAT];   // aggregated neighbor features
__device__ float g_h  [NN*DFEAT];   // conv1 output (gated in place by pool1)
__device__ float g_h2 [NN*DFEAT];   // conv2 output
__device__ float g_score[NN];       // node scores (written by GEMM epilogue)
__device__ int   g_deg[NN];
__device__ int   g_bucket[NN*BUCKET_CAP];
__device__ int   g_ovf_cnt;
__device__ int   g_ovf_d[EDGES];
__device__ int   g_ovf_s[EDGES];
__device__ unsigned char g_m1[NN];
__device__ float g_x1[BGRAPH*256];
__device__ float g_x2[BGRAPH*256];

// ---------------- packed fp32x2 helpers (Blackwell) ----------------
__device__ __forceinline__ unsigned long long pk2(float x) {
    unsigned long long d;
    asm("mov.b64 %0, {%1, %1};" : "=l"(d) : "f"(x));
    return d;
}
__device__ __forceinline__ unsigned long long ffma2(unsigned long long a,
                                                    unsigned long long b,
                                                    unsigned long long c) {
    unsigned long long d;
    asm("fma.rn.f32x2 %0, %1, %2, %3;" : "=l"(d) : "l"(a), "l"(b), "l"(c));
    return d;
}
__device__ __forceinline__ void unpk2(unsigned long long v, float& lo, float& hi) {
    asm("mov.b64 {%0, %1}, %2;" : "=f"(lo), "=f"(hi) : "l"(v));
}

// ---------------- bucketed edge build ----------------
__global__ void zero_kernel() {
    int i = blockIdx.x * blockDim.x + threadIdx.x;
    if (i < NN) g_deg[i] = 0;
    if (i == 0) g_ovf_cnt = 0;
}

__global__ void bucket_scatter_kernel(const int* __restrict__ src,
                                      const int* __restrict__ dst) {
    int i = blockIdx.x * blockDim.x + threadIdx.x;
    if (i < EDGES) {
        int d = dst[i];
        int s = src[i];
        int pos = atomicAdd(&g_deg[d], 1);
        if (pos < BUCKET_CAP) {
            g_bucket[d * BUCKET_CAP + pos] = s;
        } else {
            int o = atomicAdd(&g_ovf_cnt, 1);
            g_ovf_d[o] = d;
            g_ovf_s[o] = s;
        }
    }
}

// ---------------- neighbor aggregation: warp/node, bucket idx, MLP=8 ----------------
template<int LAYER>
__global__ void __launch_bounds__(256)
agg_gather_kernel(const float* __restrict__ xin) {
    const float* feat = (LAYER == 1) ? xin : g_h;
    int gw = (blockIdx.x * blockDim.x + threadIdx.x) >> 5;
    int lane = threadIdx.x & 31;
    if (gw >= NN) return;

    int nv = __ldg(&g_deg[gw]);
    int m = min(nv, BUCKET_CAP);
    int idx = 0;
    if (lane < m) idx = __ldg(&g_bucket[gw * BUCKET_CAP + lane]);

    const float4* f4 = (const float4*)feat;
    float a0 = 0.f, a1 = 0.f, a2 = 0.f, a3 = 0.f;
    int e = 0;
    for (; e + 8 <= m; e += 8) {
        int i0 = __shfl_sync(0xffffffffu, idx, e);
        int i1 = __shfl_sync(0xffffffffu, idx, e + 1);
        int i2 = __shfl_sync(0xffffffffu, idx, e + 2);
        int i3 = __shfl_sync(0xffffffffu, idx, e + 3);
        int i4 = __shfl_sync(0xffffffffu, idx, e + 4);
        int i5 = __shfl_sync(0xffffffffu, idx, e + 5);
        int i6 = __shfl_sync(0xffffffffu, idx, e + 6);
        int i7 = __shfl_sync(0xffffffffu, idx, e + 7);
        float4 v0 = __ldg(f4 + (size_t)i0 * 32 + lane);
        float4 v1 = __ldg(f4 + (size_t)i1 * 32 + lane);
        float4 v2 = __ldg(f4 + (size_t)i2 * 32 + lane);
        float4 v3 = __ldg(f4 + (size_t)i3 * 32 + lane);
        float4 v4 = __ldg(f4 + (size_t)i4 * 32 + lane);
        float4 v5 = __ldg(f4 + (size_t)i5 * 32 + lane);
        float4 v6 = __ldg(f4 + (size_t)i6 * 32 + lane);
        float4 v7 = __ldg(f4 + (size_t)i7 * 32 + lane);
        a0 += ((v0.x + v1.x) + (v2.x + v3.x)) + ((v4.x + v5.x) + (v6.x + v7.x));
        a1 += ((v0.y + v1.y) + (v2.y + v3.y)) + ((v4.y + v5.y) + (v6.y + v7.y));
        a2 += ((v0.z + v1.z) + (v2.z + v3.z)) + ((v4.z + v5.z) + (v6.z + v7.z));
        a3 += ((v0.w + v1.w) + (v2.w + v3.w)) + ((v4.w + v5.w) + (v6.w + v7.w));
    }
    for (; e + 4 <= m; e += 4) {
        int i0 = __shfl_sync(0xffffffffu, idx, e);
        int i1 = __shfl_sync(0xffffffffu, idx, e + 1);
        int i2 = __shfl_sync(0xffffffffu, idx, e + 2);
        int i3 = __shfl_sync(0xffffffffu, idx, e + 3);
        float4 v0 = __ldg(f4 + (size_t)i0 * 32 + lane);
        float4 v1 = __ldg(f4 + (size_t)i1 * 32 + lane);
        float4 v2 = __ldg(f4 + (size_t)i2 * 32 + lane);
        float4 v3 = __ldg(f4 + (size_t)i3 * 32 + lane);
        a0 += (v0.x + v1.x) + (v2.x + v3.x);
        a1 += (v0.y + v1.y) + (v2.y + v3.y);
        a2 += (v0.z + v1.z) + (v2.z + v3.z);
        a3 += (v0.w + v1.w) + (v2.w + v3.w);
    }
    for (; e < m; ++e) {
        int i0 = __shfl_sync(0xffffffffu, idx, e);
        float4 v0 = __ldg(f4 + (size_t)i0 * 32 + lane);
        a0 += v0.x; a1 += v0.y; a2 += v0.z; a3 += v0.w;
    }
    if (nv > BUCKET_CAP) {   // correctness fallback; ~never taken
        int oc = g_ovf_cnt;
        for (int t = 0; t < oc; ++t) {
            if (g_ovf_d[t] == gw) {
                float4 v0 = __ldg(f4 + (size_t)g_ovf_s[t] * 32 + lane);
                a0 += v0.x; a1 += v0.y; a2 += v0.z; a3 += v0.w;
            }
        }
    }
    ((float4*)g_agg)[(size_t)gw * 32 + lane] = make_float4(a0, a1, a2, a3);
}

// ---------------- conv GEMM: out = relu(A1@Wr + A2@Wn + b); score epilogue ----
// Tile 128x128, K=256, 256 threads, f32x2 packed FMA.
// Manually 2x-unrolled double buffer: static smem addressing (round-7 lesson),
// LDG(next) issued before FMA(cur) so latency is hidden, 1 barrier per chunk.

#define CONV_PREFETCH(NC)                                                     \
    {                                                                         \
        const float* A_ = ((NC) < 16) ? A1 : A2;                              \
        const float* W_ = ((NC) < 16) ? Wr : Wn;                              \
        int k0_ = ((NC) & 15) * 8;                                            \
        av = *(const float4*)&A_[(size_t)(row0 + lrow) * 128 + k0_ + lk4];    \
        wv = *(const float4*)&W_[(size_t)(k0_ + ry) * 128 + cx * 4];          \
    }

#define CONV_STS(ASB, WSB)                                                    \
    {                                                                         \
        ASB[lk4 + 0][lrow] = av.x;                                            \
        ASB[lk4 + 1][lrow] = av.y;                                            \
        ASB[lk4 + 2][lrow] = av.z;                                            \
        ASB[lk4 + 3][lrow] = av.w;                                            \
        *(float4*)&WSB[ry][cx * 4] = wv;                                      \
    }

#define CONV_COMPUTE(ASB, WSB)                                                \
    _Pragma("unroll")                                                         \
    for (int k = 0; k < 8; ++k) {                                             \
        unsigned long long ap[8];                                             \
        _Pragma("unroll")                                                     \
        for (int r = 0; r < 8; ++r)                                           \
            ap[r] = *(const unsigned long long*)&ASB[k][ry * 16 + 2 * r];     \
        _Pragma("unroll")                                                     \
        for (int j = 0; j < 4; ++j) {                                         \
            unsigned long long wp = pk2(WSB[k][cx + 32 * j]);                 \
            _Pragma("unroll")                                                 \
            for (int r = 0; r < 8; ++r)                                       \
                acc[r][j] = ffma2(ap[r], wp, acc[r][j]);                      \
        }                                                                     \
    }

template<int LAYER>
__global__ void __launch_bounds__(256, 2)
conv_gemm_kernel(const float* __restrict__ A1in,
                 const float* __restrict__ Wr,
                 const float* __restrict__ Wn,
                 const float* __restrict__ bias,
                 const float* __restrict__ p) {
    const float* A1 = (LAYER == 1) ? A1in : g_h;
    const float* A2 = g_agg;
    float* Out = (LAYER == 1) ? g_h : g_h2;

    __shared__ float As0[8][128];
    __shared__ float Ws0[8][128];
    __shared__ float As1[8][128];
    __shared__ float Ws1[8][128];

    int tid = threadIdx.x;
    int cx = tid & 31;        // column group: cols cx + 32*j
    int ry = tid >> 5;        // row group: rows ry*16 .. ry*16+15 (8 pairs)
    int row0 = blockIdx.x * 128;
    int lrow = tid >> 1;              // A loader row 0..127
    int lk4 = (tid & 1) * 4;          // A loader k sub-offset

    unsigned long long acc[8][4];
#pragma unroll
    for (int r = 0; r < 8; ++r)
#pragma unroll
        for (int j = 0; j < 4; ++j) acc[r][j] = 0ull;

    float4 av, wv;

    // preload chunk 0 into buffer 0
    CONV_PREFETCH(0);
    CONV_STS(As0, Ws0);
    __syncthreads();

#pragma unroll 1
    for (int c2 = 0; c2 < 16; ++c2) {
        int c0 = 2 * c2;

        // half A: prefetch chunk c0+1, compute buf0, stage into buf1
        CONV_PREFETCH(c0 + 1);
        CONV_COMPUTE(As0, Ws0);
        CONV_STS(As1, Ws1);
        __syncthreads();

        // half B: prefetch chunk c0+2 (except last), compute buf1, stage buf0
        if (c2 < 15) {
            CONV_PREFETCH(c0 + 2);
        }
        CONV_COMPUTE(As1, Ws1);
        if (c2 < 15) {
            CONV_STS(As0, Ws0);
            __syncthreads();
        }
    }

    // ---- epilogue: bias + relu + per-row score (h . p / ||p||) ----
    float pv[4];
    float pn = 0.f;
#pragma unroll
    for (int j = 0; j < 4; ++j) {
        pv[j] = __ldg(&p[cx + 32 * j]);
        pn += pv[j] * pv[j];
    }
#pragma unroll
    for (int o = 16; o; o >>= 1) pn += __shfl_xor_sync(0xffffffffu, pn, o);
    float pinv = rsqrtf(pn);

#pragma unroll
    for (int r = 0; r < 8; ++r) {
        float slo = 0.f, shi = 0.f;
        int row = row0 + ry * 16 + 2 * r;
#pragma unroll
        for (int j = 0; j < 4; ++j) {
            int col = cx + 32 * j;
            float bb = __ldg(&bias[col]);
            float lo, hi;
            unpk2(acc[r][j], lo, hi);
            lo = fmaxf(lo + bb, 0.f);
            hi = fmaxf(hi + bb, 0.f);
            Out[(size_t)row * 128 + col]       = lo;
            Out[(size_t)(row + 1) * 128 + col] = hi;
            slo += lo * pv[j];
            shi += hi * pv[j];
        }
#pragma unroll
        for (int o = 16; o; o >>= 1) {
            slo += __shfl_xor_sync(0xffffffffu, slo, o);
            shi += __shfl_xor_sync(0xffffffffu, shi, o);
        }
        if (cx == 0) {
            g_score[row]     = slo * pinv;
            g_score[row + 1] = shi * pinv;
        }
    }
}

// ---------------- pool: topk + gate + readout (one block per graph) ----------------
template<int LAYER>
__global__ void __launch_bounds__(512)
pool_kernel() {
    constexpr int KK = (LAYER == 1) ? KEEP1 : KEEP2;
    float* h = (LAYER == 1) ? g_h : g_h2;
    float* xout = (LAYER == 1) ? g_x1 : g_x2;

    int b = blockIdx.x;
    int tid = threadIdx.x;
    int lane = tid & 31, w = tid >> 5;   // 16 warps

    __shared__ float sval[512];
    __shared__ float ssort[512];
    __shared__ float sgate[512];
    __shared__ int   ssel[512];
    __shared__ int   sscan[512];
    __shared__ float rmax[16 * 128];
    __shared__ float rsum[16 * 128];

    float* hb = h + (size_t)b * NNODE * 128;

    // scores: precomputed by GEMM epilogue
    {
        float s = g_score[b * NNODE + tid];
        if (LAYER == 2 && !g_m1[b * NNODE + tid]) s = -INFINITY;
        sval[tid] = s;
        ssort[tid] = s;
    }
    __syncthreads();

    // bitonic sort (descending) to find threshold = K-th largest
    for (int k2 = 2; k2 <= 512; k2 <<= 1) {
        for (int j = k2 >> 1; j > 0; j >>= 1) {
            int ixj = tid ^ j;
            float a = ssort[tid];
            float bv = ssort[ixj];
            bool desc = ((tid & k2) == 0);
            bool isLower = (tid < ixj);
            float res = (desc == isLower) ? fmaxf(a, bv) : fminf(a, bv);
            __syncthreads();
            ssort[tid] = res;
            __syncthreads();
        }
    }
    float t = ssort[KK - 1];

    // exact selection with lowest-index tie-break (matches lax.top_k)
    float s = sval[tid];
    int fgt = (s > t) ? 1 : 0;
    int feq = (s == t) ? 1 : 0;
    sscan[tid] = (fgt << 16) | feq;
    __syncthreads();
    for (int off = 1; off < 512; off <<= 1) {
        int v = (tid >= off) ? sscan[tid - off] : 0;
        __syncthreads();
        sscan[tid] += v;
        __syncthreads();
    }
    int totgt = sscan[511] >> 16;
    int preeq = (sscan[tid] & 0xffff) - feq;
    int sel = fgt | (feq && (preeq < KK - totgt));
    ssel[tid] = sel;
    sgate[tid] = sel ? tanhf(s) : 0.f;
    if (LAYER == 1) g_m1[b * NNODE + tid] = (unsigned char)sel;
    __syncthreads();

    // gate (+writeback for layer1) + readout (max & mean over kept nodes)
    float mx0 = -INFINITY, mx1 = -INFINITY, mx2 = -INFINITY, mx3 = -INFINITY;
    float sm0 = 0.f, sm1 = 0.f, sm2 = 0.f, sm3 = 0.f;
    for (int n = w; n < NNODE; n += 16) {
        float g = sgate[n];
        int se = ssel[n];
        float* r = hb + n * 128;
        float v0 = r[lane] * g;
        float v1 = r[lane + 32] * g;
        float v2 = r[lane + 64] * g;
        float v3 = r[lane + 96] * g;
        if (LAYER == 1) {
            r[lane] = v0; r[lane + 32] = v1; r[lane + 64] = v2; r[lane + 96] = v3;
        }
        if (se) {
            mx0 = fmaxf(mx0, v0); mx1 = fmaxf(mx1, v1);
            mx2 = fmaxf(mx2, v2); mx3 = fmaxf(mx3, v3);
        }
        sm0 += v0; sm1 += v1; sm2 += v2; sm3 += v3;
    }
    rmax[w * 128 + lane]      = mx0;
    rmax[w * 128 + lane + 32] = mx1;
    rmax[w * 128 + lane + 64] = mx2;
    rmax[w * 128 + lane + 96] = mx3;
    rsum[w * 128 + lane]      = sm0;
    rsum[w * 128 + lane + 32] = sm1;
    rsum[w * 128 + lane + 64] = sm2;
    rsum[w * 128 + lane + 96] = sm3;
    __syncthreads();
    if (tid < 128) {
        float M = -INFINITY, S = 0.f;
#pragma unroll
        for (int i = 0; i < 16; ++i) {
            M = fmaxf(M, rmax[i * 128 + tid]);
            S += rsum[i * 128 + tid];
        }
        xout[b * 256 + tid] = M;
        xout[b * 256 + 128 + tid] = S / (float)KK;
    }
}

// ---------------- MLP head ----------------
__global__ void __launch_bounds__(128)
head_kernel(const float* __restrict__ lw1, const float* __restrict__ lb1,
            const float* __restrict__ lw2, const float* __restrict__ lb2,
            const float* __restrict__ lw3, const float* __restrict__ lb3,
            float* __restrict__ out) {
    int b = blockIdx.x;
    int tid = threadIdx.x;   // 128
    __shared__ float z[256], z1[128], z2[64];
    z[tid]       = g_x1[b * 256 + tid]       + g_x2[b * 256 + tid];
    z[tid + 128] = g_x1[b * 256 + 128 + tid] + g_x2[b * 256 + 128 + tid];
    __syncthreads();
    float a = lb1[tid];
#pragma unroll 8
    for (int i = 0; i < 256; ++i) a += z[i] * lw1[i * 128 + tid];
    z1[tid] = fmaxf(a, 0.f);
    __syncthreads();
    if (tid < 64) {
        float a2 = lb2[tid];
#pragma unroll 8
        for (int i = 0; i < 128; ++i) a2 += z1[i] * lw2[i * 64 + tid];
        z2[tid] = fmaxf(a2, 0.f);
    }
    __syncthreads();
    if (tid == 0) {
        float a3 = lb3[0];
#pragma unroll 8
        for (int i = 0; i < 64; ++i) a3 += z2[i] * lw3[i];
        out[b] = 1.f / (1.f + expf(-a3));
    }
}

// ---------------- launch ----------------
extern "C" void kernel_launch(void* const* d_in, const int* in_sizes, int n_in,
                              void* d_out, int out_size) {
    const float* x   = (const float*)d_in[0];
    const int*   ei  = (const int*)d_in[1];
    const float* W1r = (const float*)d_in[2];
    const float* W1n = (const float*)d_in[3];
    const float* b1  = (const float*)d_in[4];
    const float* p1  = (const float*)d_in[5];
    const float* W2r = (const float*)d_in[6];
    const float* W2n = (const float*)d_in[7];
    const float* b2  = (const float*)d_in[8];
    const float* p2  = (const float*)d_in[9];
    const float* lw1 = (const float*)d_in[10];
    const float* lb1 = (const float*)d_in[11];
    const float* lw2 = (const float*)d_in[12];
    const float* lb2 = (const float*)d_in[13];
    const float* lw3 = (const float*)d_in[14];
    const float* lb3 = (const float*)d_in[15];
    float* out = (float*)d_out;

    const int* src = ei;
    const int* dst = ei + EDGES;

    // edge buckets (edges are an input, rebuilt every call — stateless)
    zero_kernel<<<NN / 256, 256>>>();
    bucket_scatter_kernel<<<EDGES / 256, 256>>>(src, dst);

    // conv1 + pool1
    agg_gather_kernel<1><<<NN * 32 / 256, 256>>>(x);
    conv_gemm_kernel<1><<<NN / 128, 256>>>(x, W1r, W1n, b1, p1);
    pool_kernel<1><<<BGRAPH, 512>>>();

    // conv2 + pool2 (on gated h)
    agg_gather_kernel<2><<<NN * 32 / 256, 256>>>(nullptr);
    conv_gemm_kernel<2><<<NN / 128, 256>>>(nullptr, W2r, W2n, b2, p2);
    pool_kernel<2><<<BGRAPH, 512>>>();

    // head
    head_kernel<<<BGRAPH, 128>>>(lw1, lb1, lw2, lb2, lw3, lb3, out);
}